// round 16
// baseline (speedup 1.0000x reference)
#include <cuda_runtime.h>
#include <cuda_fp16.h>
#include <math.h>
#include <float.h>
#include <stdint.h>

#define DIMD  1024
#define NSEQ  2048
#define NROWS 16384
#define NOUT  (NROWS * DIMD)

#define LO_SCALE   2048.0f
#define LO_INV     4.8828125e-4f   // 1/2048, exact

// ---------------- static device scratch ----------------
__device__ __half g_xhi[2 * NROWS * DIMD];
__device__ __half g_xlo[2 * NROWS * DIMD];      // residual * 2048
__device__ __half g_wthi[3072 * DIMD];          // W^T [n][k]
__device__ __half g_wtlo[3072 * DIMD];          // residual * 2048
__device__ __half g_qhi[2 * NROWS * DIMD];
__device__ __half g_qlo[2 * NROWS * DIMD];      // residual * 2048
__device__ __half g_khi[2 * NROWS * DIMD];
__device__ __half g_klo[2 * NROWS * DIMD];      // residual * 2048
__device__ float  g_v[2 * NROWS * DIMD];
__device__ float  g_s[16 * NSEQ * NSEQ];        // exact logits [d*8+b][q][k]

// ---------------- helpers ----------------
__device__ __forceinline__ uint32_t smem_u32(const void* p) {
    uint32_t a;
    asm("{ .reg .u64 t; cvta.to.shared.u64 t, %1; cvt.u32.u64 %0, t; }" : "=r"(a) : "l"(p));
    return a;
}

#define CP16(dst, src)  asm volatile("cp.async.cg.shared.global [%0], [%1], 16;" :: "r"(dst), "l"(src))
#define CP_COMMIT()     asm volatile("cp.async.commit_group;" ::: "memory")
#define CP_WAIT(n)      asm volatile("cp.async.wait_group %0;" :: "n"(n) : "memory")

__device__ __forceinline__ void ldsm4(uint32_t* r, uint32_t a) {
    asm volatile("ldmatrix.sync.aligned.m8n8.x4.shared.b16 {%0,%1,%2,%3}, [%4];"
                 : "=r"(r[0]), "=r"(r[1]), "=r"(r[2]), "=r"(r[3]) : "r"(a));
}

__device__ __forceinline__ void mma16816(float* c, const uint32_t* a, const uint32_t* b) {
    asm volatile("mma.sync.aligned.m16n8k16.row.col.f32.f16.f16.f32 "
                 "{%0,%1,%2,%3},{%4,%5,%6,%7},{%8,%9},{%0,%1,%2,%3};"
                 : "+f"(c[0]), "+f"(c[1]), "+f"(c[2]), "+f"(c[3])
                 : "r"(a[0]), "r"(a[1]), "r"(a[2]), "r"(a[3]), "r"(b[0]), "r"(b[1]));
}

// split x = hi + lo/2048  (lo stored pre-scaled: stays in fp16 normal range)
__device__ __forceinline__ uint32_t pack_split(float a, float b, uint32_t& lo) {
    __half ha = __float2half_rn(a), hb = __float2half_rn(b);
    __half la = __float2half_rn((a - __half2float(ha)) * LO_SCALE);
    __half lb = __float2half_rn((b - __half2float(hb)) * LO_SCALE);
    lo = (uint32_t)__half_as_ushort(la) | ((uint32_t)__half_as_ushort(lb) << 16);
    return (uint32_t)__half_as_ushort(ha) | ((uint32_t)__half_as_ushort(hb) << 16);
}

// SMEM: 2 buffers x 64KB.  Buffer: Ahi(16K) Alo(16K) Bhi(16K) Blo(16K).
// All tiles 128 rows x 64 halves (128B rows), 16B-chunk swizzle.  512 threads.
#define SM_BUF   65536
#define SM_TOTAL (2 * SM_BUF)

__device__ __forceinline__ void load_tile(uint32_t sb, const __half* base, int tid) {
#pragma unroll
    for (int i = 0; i < 2; i++) {
        const int ch  = tid + i * 512;
        const int row = ch >> 3, c = ch & 7;
        const uint32_t d = sb + row * 128 + ((c ^ (row & 7)) << 4);
        CP16(d, base + (size_t)row * DIMD + c * 8);
    }
}

// NTERMS: 1 = Ahi*Bhi ; 3 = + Ahi*Blo + Alo*Bhi
template<int NTERMS>
__device__ __forceinline__ void load4(uint32_t smbuf,
                                      const __half* Ahi, const __half* Alo,
                                      const __half* Bhi, const __half* Blo,
                                      int kc, int tid) {
    load_tile(smbuf,         Ahi + kc * 64, tid);
    if (NTERMS == 3)
        load_tile(smbuf + 16384, Alo + kc * 64, tid);
    load_tile(smbuf + 32768, Bhi + kc * 64, tid);
    if (NTERMS >= 2)
        load_tile(smbuf + 49152, Blo + kc * 64, tid);
}

// Scaled-split mainloop, CTA tile 128x128, warp tile 32x32 (warps 4x4, 512 thr).
template<int NTERMS>
__device__ __forceinline__ void mainloop(float chh[2][4][4], float ccr[2][4][4],
                                         uint32_t sm0,
                                         const __half* Ahi, const __half* Alo,
                                         const __half* Bhi, const __half* Blo,
                                         int tid) {
    const int lane = tid & 31, w = tid >> 5;
    const int wR = w >> 2, wC = w & 3;

    uint32_t aBase[2]; int aXor[2];
    const int cA = lane >> 4;
#pragma unroll
    for (int mt = 0; mt < 2; mt++) {
        const int r = wR * 32 + mt * 16 + (lane & 15);
        aBase[mt] = r * 128; aXor[mt] = r & 7;
    }
    uint32_t bBase[2]; int bXor[2];
    const int qg = lane >> 3;
    const int cB = qg & 1;
#pragma unroll
    for (int g = 0; g < 2; g++) {
        const int nt = g * 2 + (qg >> 1);
        const int r = wC * 32 + nt * 8 + (lane & 7);
        bBase[g] = r * 128; bXor[g] = r & 7;
    }

#pragma unroll
    for (int mt = 0; mt < 2; mt++)
#pragma unroll
        for (int nt = 0; nt < 4; nt++)
#pragma unroll
            for (int i = 0; i < 4; i++) { chh[mt][nt][i] = 0.f; ccr[mt][nt][i] = 0.f; }

    load4<NTERMS>(sm0, Ahi, Alo, Bhi, Blo, 0, tid);
    CP_COMMIT();

#pragma unroll 1
    for (int kc = 0; kc < 16; kc++) {
        const uint32_t buf = sm0 + (kc & 1) * SM_BUF;
        CP_WAIT(0);
        __syncthreads();
        if (kc + 1 < 16) {
            load4<NTERMS>(sm0 + ((kc + 1) & 1) * SM_BUF, Ahi, Alo, Bhi, Blo, kc + 1, tid);
            CP_COMMIT();
        }

#pragma unroll
        for (int ks = 0; ks < 4; ks++) {
            uint32_t bh[8], bl[8];
#pragma unroll
            for (int g = 0; g < 2; g++) {
                const uint32_t off = bBase[g] + (uint32_t)((((ks << 1) + cB) ^ bXor[g]) << 4);
                ldsm4(&bh[g * 4], buf + 32768 + off);
                if (NTERMS >= 2) ldsm4(&bl[g * 4], buf + 49152 + off);
            }
#pragma unroll
            for (int mt = 0; mt < 2; mt++) {
                uint32_t ah[4], al[4];
                const uint32_t off = aBase[mt] + (uint32_t)((((ks << 1) + cA) ^ aXor[mt]) << 4);
                ldsm4(ah, buf + off);
                if (NTERMS == 3) ldsm4(al, buf + 16384 + off);
#pragma unroll
                for (int nt = 0; nt < 4; nt++) mma16816(chh[mt][nt], ah, &bh[nt * 2]);
                if (NTERMS >= 2) {
#pragma unroll
                    for (int nt = 0; nt < 4; nt++) mma16816(ccr[mt][nt], ah, &bl[nt * 2]);
                }
                if (NTERMS == 3) {
#pragma unroll
                    for (int nt = 0; nt < 4; nt++) mma16816(ccr[mt][nt], al, &bh[nt * 2]);
                }
            }
        }
    }
}

// ---------------- GEMM 1: QKV projection ----------------
__global__ void __launch_bounds__(512, 1) gemm_qkv_tc() {
    extern __shared__ char smem[];
    const int tid = threadIdx.x, lane = tid & 31, w = tid >> 5;
    const int wR = w >> 2, wC = w & 3;
    const uint32_t sm0 = smem_u32(smem);

    const int nTile = blockIdx.x;   // 0..23 (128 cols each of 3072)
    const int mTile = blockIdx.y;   // 0..127
    const int feat  = blockIdx.z;   // 0..1

    const size_t aB = ((size_t)feat * NROWS + (size_t)mTile * 128) * DIMD;
    const size_t bB = (size_t)nTile * 128 * DIMD;

    const int sect = nTile >> 3;            // 0=Q 1=K 2=V

    float chh[2][4][4], ccr[2][4][4];
    if (sect == 2)  // V error budget ~1e-3 direct: 1-term suffices (~3e-4)
        mainloop<1>(chh, ccr, sm0, g_xhi + aB, g_xlo + aB, g_wthi + bB, g_wtlo + bB, tid);
    else            // Q/K feed exact-logit scores: full 3-term
        mainloop<3>(chh, ccr, sm0, g_xhi + aB, g_xlo + aB, g_wthi + bB, g_wtlo + bB, tid);

    const int colb = (nTile & 7) * 128;
#pragma unroll
    for (int mt = 0; mt < 2; mt++) {
        const size_t tr = (size_t)feat * NROWS + (size_t)mTile * 128 + wR * 32 + mt * 16 + (lane >> 2);
#pragma unroll
        for (int nt = 0; nt < 4; nt++) {
            const int col = colb + wC * 32 + nt * 8 + 2 * (lane & 3);
            if (sect == 2) {
                *(float2*)&g_v[tr * DIMD + col]       = make_float2(chh[mt][nt][0], chh[mt][nt][1]);
                *(float2*)&g_v[(tr + 8) * DIMD + col] = make_float2(chh[mt][nt][2], chh[mt][nt][3]);
            } else {
                float v0 = chh[mt][nt][0] + ccr[mt][nt][0] * LO_INV;
                float v1 = chh[mt][nt][1] + ccr[mt][nt][1] * LO_INV;
                float v2 = chh[mt][nt][2] + ccr[mt][nt][2] * LO_INV;
                float v3 = chh[mt][nt][3] + ccr[mt][nt][3] * LO_INV;
                __half* dh = sect ? g_khi : g_qhi;
                __half* dl = sect ? g_klo : g_qlo;
                uint32_t lo0, lo1;
                const uint32_t hi0 = pack_split(v0, v1, lo0);
                const uint32_t hi1 = pack_split(v2, v3, lo1);
                *(uint32_t*)&dh[tr * DIMD + col]       = hi0;
                *(uint32_t*)&dl[tr * DIMD + col]       = lo0;
                *(uint32_t*)&dh[(tr + 8) * DIMD + col] = hi1;
                *(uint32_t*)&dl[(tr + 8) * DIMD + col] = lo1;
            }
        }
    }
}

// ---------------- GEMM 2: scores (3-term exact logits) ----------------
__global__ void __launch_bounds__(512, 1) gemm_scores_tc() {
    extern __shared__ char smem[];
    const int tid = threadIdx.x, lane = tid & 31, w = tid >> 5;
    const int wR = w >> 2, wC = w & 3;
    const uint32_t sm0 = smem_u32(smem);

    const int nTile = blockIdx.x;   // 0..15 key tiles (128 keys each)
    const int mTile = blockIdx.y;   // 0..15 query tiles
    const int z     = blockIdx.z;   // d*8+b
    const int d     = z >> 3;
    const int b     = z & 7;

    const size_t aB = ((size_t)d * NROWS + (size_t)b * NSEQ + (size_t)mTile * 128) * DIMD;
    const size_t bB = ((size_t)(1 - d) * NROWS + (size_t)b * NSEQ + (size_t)nTile * 128) * DIMD;

    float chh[2][4][4], ccr[2][4][4];
    mainloop<3>(chh, ccr, sm0, g_qhi + aB, g_qlo + aB, g_khi + bB, g_klo + bB, tid);

    const float scale = 0.03125f;
    float* S = g_s + (size_t)z * NSEQ * NSEQ;
#pragma unroll
    for (int mt = 0; mt < 2; mt++) {
        const size_t qr = (size_t)mTile * 128 + wR * 32 + mt * 16 + (lane >> 2);
#pragma unroll
        for (int nt = 0; nt < 4; nt++) {
            const int col = nTile * 128 + wC * 32 + nt * 8 + 2 * (lane & 3);
            float v0 = (chh[mt][nt][0] + ccr[mt][nt][0] * LO_INV) * scale;
            float v1 = (chh[mt][nt][1] + ccr[mt][nt][1] * LO_INV) * scale;
            float v2 = (chh[mt][nt][2] + ccr[mt][nt][2] * LO_INV) * scale;
            float v3 = (chh[mt][nt][3] + ccr[mt][nt][3] * LO_INV) * scale;
            *(float2*)&S[qr * NSEQ + col]       = make_float2(v0, v1);
            *(float2*)&S[(qr + 8) * NSEQ + col] = make_float2(v2, v3);
        }
    }
}

// ---------------- conversions ----------------
__global__ void __launch_bounds__(256) conv_x_kernel(const float* __restrict__ f1,
                                                     const float* __restrict__ f2) {
    const float* src = blockIdx.y ? f2 : f1;
    const size_t i4 = (size_t)blockIdx.x * 256 + threadIdx.x;
    float4 v = ((const float4*)src)[i4];
    uint32_t lo0, lo1;
    const uint32_t hi0 = pack_split(v.x, v.y, lo0);
    const uint32_t hi1 = pack_split(v.z, v.w, lo1);
    const size_t off = (size_t)blockIdx.y * NROWS * DIMD;
    ((uint2*)(g_xhi + off))[i4] = make_uint2(hi0, hi1);
    ((uint2*)(g_xlo + off))[i4] = make_uint2(lo0, lo1);
}

__global__ void __launch_bounds__(256) conv_wt_kernel(const float* __restrict__ W) {
    __shared__ float t[32][33];
    const int n0 = blockIdx.x * 32;
    const int k0 = blockIdx.y * 32;
    const int tx = threadIdx.x, ty = threadIdx.y;   // block (32, 8)
#pragma unroll
    for (int r = 0; r < 4; r++)
        t[ty + r * 8][tx] = W[(size_t)(k0 + ty + r * 8) * 3072 + n0 + tx];
    __syncthreads();
#pragma unroll
    for (int r = 0; r < 4; r++) {
        const int n = n0 + ty + r * 8;
        const float x = t[tx][ty + r * 8];
        __half h = __float2half_rn(x);
        __half l = __float2half_rn((x - __half2float(h)) * LO_SCALE);
        g_wthi[(size_t)n * DIMD + k0 + tx] = h;
        g_wtlo[(size_t)n * DIMD + k0 + tx] = l;
    }
}

// ---------------- softmax + top-16 + sparse A@V ----------------
__global__ void __launch_bounds__(256) attn_out_kernel(float* __restrict__ out) {
    const int row = blockIdx.x;
    const int d   = row >> 14;
    const int rem = row & 16383;
    const int b   = rem >> 11;

    const float* s = g_s + (size_t)row * NSEQ;
    const float* V = g_v + ((size_t)(1 - d) * NROWS + (size_t)b * NSEQ) * DIMD;
    float*       o = out + (size_t)d * NOUT + (size_t)rem * DIMD;

    const int tid = threadIdx.x, lane = tid & 31, wid = tid >> 5;

    float l[8];
#pragma unroll
    for (int i = 0; i < 8; i++) l[i] = s[tid + 256 * i];

    __shared__ float sred[8];

    // ---- block max ----
    float m = l[0];
#pragma unroll
    for (int i = 1; i < 8; i++) m = fmaxf(m, l[i]);
#pragma unroll
    for (int off = 16; off; off >>= 1) m = fmaxf(m, __shfl_xor_sync(0xffffffffu, m, off));
    if (!lane) sred[wid] = m;
    __syncthreads();
    m = sred[0];
#pragma unroll
    for (int j = 1; j < 8; j++) m = fmaxf(m, sred[j]);
    __syncthreads();

    // ---- block sum of exp ----
    float se = 0.f;
#pragma unroll
    for (int i = 0; i < 8; i++) se += expf(l[i] - m);
#pragma unroll
    for (int off = 16; off; off >>= 1) se += __shfl_xor_sync(0xffffffffu, se, off);
    if (!lane) sred[wid] = se;
    __syncthreads();
    float denom = sred[0];
#pragma unroll
    for (int j = 1; j < 8; j++) denom += sred[j];
    const float invDen = 1.0f / denom;

    // ---- per-warp top-16 (barrier-free), then single-warp merge ----
    __shared__ float wv[8][16];
    __shared__ int   wi[8][16];
    __shared__ float selv[16];
    __shared__ int   seli[16];
    __shared__ float selw[16];

    float cur[8];
#pragma unroll
    for (int i = 0; i < 8; i++) cur[i] = l[i];

    for (int it = 0; it < 16; ++it) {
        float bv = cur[0];
        int   bi = tid;
#pragma unroll
        for (int i = 1; i < 8; i++) {
            const int idx = tid + 256 * i;
            if (cur[i] > bv || (cur[i] == bv && idx < bi)) { bv = cur[i]; bi = idx; }
        }
#pragma unroll
        for (int off = 16; off; off >>= 1) {
            const float ov = __shfl_xor_sync(0xffffffffu, bv, off);
            const int   oi = __shfl_xor_sync(0xffffffffu, bi, off);
            if (ov > bv || (ov == bv && oi < bi)) { bv = ov; bi = oi; }
        }
        if (!lane) { wv[wid][it] = bv; wi[wid][it] = bi; }
        if ((bi & 255) == tid) cur[bi >> 8] = -FLT_MAX;   // clear winner (owner thread)
    }
    __syncthreads();

    if (wid == 0) {
        // 128 candidates (8 warps x 16); merge top-16
        float cv[4]; int ci[4];
#pragma unroll
        for (int j = 0; j < 4; j++) {
            const int c = lane * 4 + j;
            cv[j] = wv[c >> 4][c & 15];
            ci[j] = wi[c >> 4][c & 15];
        }
        for (int it = 0; it < 16; ++it) {
            float bv = cv[0]; int bi = ci[0];
#pragma unroll
            for (int j = 1; j < 4; j++)
                if (cv[j] > bv || (cv[j] == bv && ci[j] < bi)) { bv = cv[j]; bi = ci[j]; }
#pragma unroll
            for (int off = 16; off; off >>= 1) {
                const float ov = __shfl_xor_sync(0xffffffffu, bv, off);
                const int   oi = __shfl_xor_sync(0xffffffffu, bi, off);
                if (ov > bv || (ov == bv && oi < bi)) { bv = ov; bi = oi; }
            }
            if (!lane) { selv[it] = bv; seli[it] = bi; }
#pragma unroll
            for (int j = 0; j < 4; j++)
                if (ci[j] == bi) cv[j] = -FLT_MAX;
        }
        __syncwarp();
        if (lane < 16) selw[lane] = expf(selv[lane] - m) * invDen;
    }
    __syncthreads();

    // ---- sparse attention-weighted V gather ----
    float4 acc = make_float4(0.f, 0.f, 0.f, 0.f);
#pragma unroll
    for (int j = 0; j < 16; j++) {
        const float  w  = selw[j];
        const float4 vv = *(const float4*)(V + (size_t)seli[j] * DIMD + tid * 4);
        acc.x = fmaf(w, vv.x, acc.x);
        acc.y = fmaf(w, vv.y, acc.y);
        acc.z = fmaf(w, vv.z, acc.z);
        acc.w = fmaf(w, vv.w, acc.w);
    }
    *(float4*)(o + tid * 4) = acc;
}

// ---------------------------------------------------------------------------
extern "C" void kernel_launch(void* const* d_in, const int* in_sizes, int n_in,
                              void* d_out, int out_size) {
    const float* f1 = (const float*)d_in[0];
    const float* f2 = (const float*)d_in[1];
    const float* W  = (const float*)d_in[2];
    float* out = (float*)d_out;

    cudaFuncSetAttribute(gemm_qkv_tc, cudaFuncAttributeMaxDynamicSharedMemorySize, SM_TOTAL);
    cudaFuncSetAttribute(gemm_scores_tc, cudaFuncAttributeMaxDynamicSharedMemorySize, SM_TOTAL);

    conv_x_kernel<<<dim3(16384, 2), 256>>>(f1, f2);
    conv_wt_kernel<<<dim3(96, 32), dim3(32, 8)>>>(W);

    gemm_qkv_tc<<<dim3(24, 128, 2), 512, SM_TOTAL>>>();
    gemm_scores_tc<<<dim3(16, 16, 16), 512, SM_TOTAL>>>();

    attn_out_kernel<<<32768, 256>>>(out);
}

// round 17
// speedup vs baseline: 1.0523x; 1.0523x over previous
#include <cuda_runtime.h>
#include <cuda_fp16.h>
#include <math.h>
#include <float.h>
#include <stdint.h>

#define DIMD  1024
#define NSEQ  2048
#define NROWS 16384
#define NOUT  (NROWS * DIMD)

#define LO_SCALE   2048.0f
#define LO_INV     4.8828125e-4f   // 1/2048, exact

// ---------------- static device scratch ----------------
__device__ __half g_xhi[2 * NROWS * DIMD];
__device__ __half g_xlo[2 * NROWS * DIMD];      // residual * 2048
__device__ __half g_wthi[3072 * DIMD];          // W^T [n][k]
__device__ __half g_wtlo[3072 * DIMD];          // residual * 2048
__device__ __half g_qhi[2 * NROWS * DIMD];
__device__ __half g_qlo[2 * NROWS * DIMD];      // residual * 2048
__device__ __half g_khi[2 * NROWS * DIMD];
__device__ __half g_klo[2 * NROWS * DIMD];      // residual * 2048
__device__ float  g_v[2 * NROWS * DIMD];
__device__ float  g_s[16 * NSEQ * NSEQ];        // exact logits [d*8+b][q][k]

// ---------------- helpers ----------------
__device__ __forceinline__ uint32_t smem_u32(const void* p) {
    uint32_t a;
    asm("{ .reg .u64 t; cvta.to.shared.u64 t, %1; cvt.u32.u64 %0, t; }" : "=r"(a) : "l"(p));
    return a;
}

#define CP16(dst, src)  asm volatile("cp.async.cg.shared.global [%0], [%1], 16;" :: "r"(dst), "l"(src))
#define CP_COMMIT()     asm volatile("cp.async.commit_group;" ::: "memory")
#define CP_WAIT(n)      asm volatile("cp.async.wait_group %0;" :: "n"(n) : "memory")

__device__ __forceinline__ void ldsm4(uint32_t* r, uint32_t a) {
    asm volatile("ldmatrix.sync.aligned.m8n8.x4.shared.b16 {%0,%1,%2,%3}, [%4];"
                 : "=r"(r[0]), "=r"(r[1]), "=r"(r[2]), "=r"(r[3]) : "r"(a));
}

__device__ __forceinline__ void mma16816(float* c, const uint32_t* a, const uint32_t* b) {
    asm volatile("mma.sync.aligned.m16n8k16.row.col.f32.f16.f16.f32 "
                 "{%0,%1,%2,%3},{%4,%5,%6,%7},{%8,%9},{%0,%1,%2,%3};"
                 : "+f"(c[0]), "+f"(c[1]), "+f"(c[2]), "+f"(c[3])
                 : "r"(a[0]), "r"(a[1]), "r"(a[2]), "r"(a[3]), "r"(b[0]), "r"(b[1]));
}

// split x = hi + lo/2048  (lo stored pre-scaled: stays in fp16 normal range)
__device__ __forceinline__ uint32_t pack_split(float a, float b, uint32_t& lo) {
    __half ha = __float2half_rn(a), hb = __float2half_rn(b);
    __half la = __float2half_rn((a - __half2float(ha)) * LO_SCALE);
    __half lb = __float2half_rn((b - __half2float(hb)) * LO_SCALE);
    lo = (uint32_t)__half_as_ushort(la) | ((uint32_t)__half_as_ushort(lb) << 16);
    return (uint32_t)__half_as_ushort(ha) | ((uint32_t)__half_as_ushort(hb) << 16);
}

// Q/K GEMM SMEM: 2 buffers x 48KB.  Buffer: Ahi(16K) Alo(16K) Bhi(8K) Blo(8K).
#define SM_BUF   49152
#define SM_TOTAL (2 * SM_BUF)
// V GEMM SMEM: 2 buffers x 32KB.  Buffer: Ahi(16K) Bhi(16K).
#define SMV_BUF   32768
#define SMV_TOTAL (2 * SMV_BUF)

// 128-row x 64-half tile loader (256 threads)
__device__ __forceinline__ void load_tileA(uint32_t sb, const __half* base, int tid) {
#pragma unroll
    for (int i = 0; i < 4; i++) {
        const int ch  = tid + i * 256;
        const int row = ch >> 3, c = ch & 7;
        const uint32_t d = sb + row * 128 + ((c ^ (row & 7)) << 4);
        CP16(d, base + (size_t)row * DIMD + c * 8);
    }
}
// 64-row x 64-half tile loader (256 threads)
__device__ __forceinline__ void load_tileB(uint32_t sb, const __half* base, int tid) {
#pragma unroll
    for (int i = 0; i < 2; i++) {
        const int ch  = tid + i * 256;
        const int row = ch >> 3, c = ch & 7;
        const uint32_t d = sb + row * 128 + ((c ^ (row & 7)) << 4);
        CP16(d, base + (size_t)row * DIMD + c * 8);
    }
}

__device__ __forceinline__ void load4(uint32_t smbuf,
                                      const __half* Ahi, const __half* Alo,
                                      const __half* Bhi, const __half* Blo,
                                      int kc, int tid) {
    load_tileA(smbuf,         Ahi + kc * 64, tid);
    load_tileA(smbuf + 16384, Alo + kc * 64, tid);
    load_tileB(smbuf + 32768, Bhi + kc * 64, tid);
    load_tileB(smbuf + 40960, Blo + kc * 64, tid);
}

// 3-term scaled-split mainloop, CTA tile 128x64, warp tile 32x32 (warps 4x2).
__device__ __forceinline__ void mainloop3(float chh[2][4][4], float ccr[2][4][4],
                                          uint32_t sm0,
                                          const __half* Ahi, const __half* Alo,
                                          const __half* Bhi, const __half* Blo,
                                          int tid) {
    const int lane = tid & 31, w = tid >> 5;
    const int wR = w >> 1, wC = w & 1;

    uint32_t aBase[2]; int aXor[2];
    const int cA = lane >> 4;
#pragma unroll
    for (int mt = 0; mt < 2; mt++) {
        const int r = wR * 32 + mt * 16 + (lane & 15);
        aBase[mt] = r * 128; aXor[mt] = r & 7;
    }
    uint32_t bBase[2]; int bXor[2];
    const int qg = lane >> 3;
    const int cB = qg & 1;
#pragma unroll
    for (int g = 0; g < 2; g++) {
        const int nt = g * 2 + (qg >> 1);
        const int r = wC * 32 + nt * 8 + (lane & 7);
        bBase[g] = r * 128; bXor[g] = r & 7;
    }

#pragma unroll
    for (int mt = 0; mt < 2; mt++)
#pragma unroll
        for (int nt = 0; nt < 4; nt++)
#pragma unroll
            for (int i = 0; i < 4; i++) { chh[mt][nt][i] = 0.f; ccr[mt][nt][i] = 0.f; }

    load4(sm0, Ahi, Alo, Bhi, Blo, 0, tid);
    CP_COMMIT();

#pragma unroll 1
    for (int kc = 0; kc < 16; kc++) {
        const uint32_t buf = sm0 + (kc & 1) * SM_BUF;
        CP_WAIT(0);
        __syncthreads();
        if (kc + 1 < 16) {
            load4(sm0 + ((kc + 1) & 1) * SM_BUF, Ahi, Alo, Bhi, Blo, kc + 1, tid);
            CP_COMMIT();
        }

#pragma unroll
        for (int ks = 0; ks < 4; ks++) {
            uint32_t bh[8], bl[8];
#pragma unroll
            for (int g = 0; g < 2; g++) {
                const uint32_t off = bBase[g] + (uint32_t)((((ks << 1) + cB) ^ bXor[g]) << 4);
                ldsm4(&bh[g * 4], buf + 32768 + off);
                ldsm4(&bl[g * 4], buf + 40960 + off);
            }
#pragma unroll
            for (int mt = 0; mt < 2; mt++) {
                uint32_t ah[4], al[4];
                const uint32_t off = aBase[mt] + (uint32_t)((((ks << 1) + cA) ^ aXor[mt]) << 4);
                ldsm4(ah, buf + off);
                ldsm4(al, buf + 16384 + off);
#pragma unroll
                for (int nt = 0; nt < 4; nt++) mma16816(chh[mt][nt], ah, &bh[nt * 2]);
#pragma unroll
                for (int nt = 0; nt < 4; nt++) mma16816(ccr[mt][nt], ah, &bl[nt * 2]);
#pragma unroll
                for (int nt = 0; nt < 4; nt++) mma16816(ccr[mt][nt], al, &bh[nt * 2]);
            }
        }
    }
}

// ---------------- GEMM 1a: Q/K projection (3-term) ----------------
__global__ void __launch_bounds__(256, 2) gemm_qkv_tc() {
    extern __shared__ char smem[];
    const int tid = threadIdx.x, lane = tid & 31, w = tid >> 5;
    const int wR = w >> 1, wC = w & 1;
    const uint32_t sm0 = smem_u32(smem);

    const int nTile = blockIdx.x;   // 0..31 (64 cols each; Q cols then K cols)
    const int mTile = blockIdx.y;   // 0..127
    const int feat  = blockIdx.z;   // 0..1

    const size_t aB = ((size_t)feat * NROWS + (size_t)mTile * 128) * DIMD;
    const size_t bB = (size_t)nTile * 64 * DIMD;

    const int sect = nTile >> 4;            // 0=Q 1=K

    float chh[2][4][4], ccr[2][4][4];
    mainloop3(chh, ccr, sm0, g_xhi + aB, g_xlo + aB, g_wthi + bB, g_wtlo + bB, tid);

    const int colb = (nTile & 15) * 64;
#pragma unroll
    for (int mt = 0; mt < 2; mt++) {
        const size_t tr = (size_t)feat * NROWS + (size_t)mTile * 128 + wR * 32 + mt * 16 + (lane >> 2);
#pragma unroll
        for (int nt = 0; nt < 4; nt++) {
            const int col = colb + wC * 32 + nt * 8 + 2 * (lane & 3);
            float v0 = chh[mt][nt][0] + ccr[mt][nt][0] * LO_INV;
            float v1 = chh[mt][nt][1] + ccr[mt][nt][1] * LO_INV;
            float v2 = chh[mt][nt][2] + ccr[mt][nt][2] * LO_INV;
            float v3 = chh[mt][nt][3] + ccr[mt][nt][3] * LO_INV;
            __half* dh = sect ? g_khi : g_qhi;
            __half* dl = sect ? g_klo : g_qlo;
            uint32_t lo0, lo1;
            const uint32_t hi0 = pack_split(v0, v1, lo0);
            const uint32_t hi1 = pack_split(v2, v3, lo1);
            *(uint32_t*)&dh[tr * DIMD + col]       = hi0;
            *(uint32_t*)&dl[tr * DIMD + col]       = lo0;
            *(uint32_t*)&dh[(tr + 8) * DIMD + col] = hi1;
            *(uint32_t*)&dl[(tr + 8) * DIMD + col] = lo1;
        }
    }
}

// ---------------- GEMM 1b: V projection (1-term, 128x128 tile, 256 thr) ----------------
__global__ void __launch_bounds__(256, 2) gemm_v_tc() {
    extern __shared__ char smem[];
    const int tid = threadIdx.x, lane = tid & 31, w = tid >> 5;
    const int wR = w >> 1, wC = w & 1;       // warps 4x2, warp tile 32x64
    const uint32_t sm0 = smem_u32(smem);

    const int nTile = blockIdx.x;   // 0..7 (128 V cols each)
    const int mTile = blockIdx.y;   // 0..127
    const int feat  = blockIdx.z;   // 0..1

    const __half* Ahi = g_xhi + ((size_t)feat * NROWS + (size_t)mTile * 128) * DIMD;
    const __half* Bhi = g_wthi + (size_t)(2048 + nTile * 128) * DIMD;

    uint32_t aBase[2]; int aXor[2];
    const int cA = lane >> 4;
#pragma unroll
    for (int mt = 0; mt < 2; mt++) {
        const int r = wR * 32 + mt * 16 + (lane & 15);
        aBase[mt] = r * 128; aXor[mt] = r & 7;
    }
    uint32_t bBase[4]; int bXor[4];
    const int qg = lane >> 3;
    const int cB = qg & 1;
#pragma unroll
    for (int g = 0; g < 4; g++) {
        const int nt = g * 2 + (qg >> 1);
        const int r = wC * 64 + nt * 8 + (lane & 7);
        bBase[g] = r * 128; bXor[g] = r & 7;
    }

    float chh[2][8][4];
#pragma unroll
    for (int mt = 0; mt < 2; mt++)
#pragma unroll
        for (int nt = 0; nt < 8; nt++)
#pragma unroll
            for (int i = 0; i < 4; i++) chh[mt][nt][i] = 0.f;

    load_tileA(sm0,         Ahi, tid);
    load_tileA(sm0 + 16384, Bhi, tid);
    CP_COMMIT();

#pragma unroll 1
    for (int kc = 0; kc < 16; kc++) {
        const uint32_t buf = sm0 + (kc & 1) * SMV_BUF;
        CP_WAIT(0);
        __syncthreads();
        if (kc + 1 < 16) {
            const uint32_t nb = sm0 + ((kc + 1) & 1) * SMV_BUF;
            load_tileA(nb,         Ahi + (kc + 1) * 64, tid);
            load_tileA(nb + 16384, Bhi + (kc + 1) * 64, tid);
            CP_COMMIT();
        }

#pragma unroll
        for (int ks = 0; ks < 4; ks++) {
            uint32_t bh[16];
#pragma unroll
            for (int g = 0; g < 4; g++) {
                const uint32_t off = bBase[g] + (uint32_t)((((ks << 1) + cB) ^ bXor[g]) << 4);
                ldsm4(&bh[g * 4], buf + 16384 + off);
            }
#pragma unroll
            for (int mt = 0; mt < 2; mt++) {
                uint32_t ah[4];
                const uint32_t off = aBase[mt] + (uint32_t)((((ks << 1) + cA) ^ aXor[mt]) << 4);
                ldsm4(ah, buf + off);
#pragma unroll
                for (int nt = 0; nt < 8; nt++) mma16816(chh[mt][nt], ah, &bh[nt * 2]);
            }
        }
    }

#pragma unroll
    for (int mt = 0; mt < 2; mt++) {
        const size_t tr = (size_t)feat * NROWS + (size_t)mTile * 128 + wR * 32 + mt * 16 + (lane >> 2);
#pragma unroll
        for (int nt = 0; nt < 8; nt++) {
            const int col = nTile * 128 + wC * 64 + nt * 8 + 2 * (lane & 3);
            *(float2*)&g_v[tr * DIMD + col]       = make_float2(chh[mt][nt][0], chh[mt][nt][1]);
            *(float2*)&g_v[(tr + 8) * DIMD + col] = make_float2(chh[mt][nt][2], chh[mt][nt][3]);
        }
    }
}

// ---------------- GEMM 2: scores (3-term exact logits) ----------------
__global__ void __launch_bounds__(256, 2) gemm_scores_tc() {
    extern __shared__ char smem[];
    const int tid = threadIdx.x, lane = tid & 31, w = tid >> 5;
    const int wR = w >> 1, wC = w & 1;
    const uint32_t sm0 = smem_u32(smem);

    const int nTile = blockIdx.x;   // 0..31 key tiles (64 keys each)
    const int mTile = blockIdx.y;   // 0..15 query tiles
    const int z     = blockIdx.z;   // d*8+b
    const int d     = z >> 3;
    const int b     = z & 7;

    const size_t aB = ((size_t)d * NROWS + (size_t)b * NSEQ + (size_t)mTile * 128) * DIMD;
    const size_t bB = ((size_t)(1 - d) * NROWS + (size_t)b * NSEQ + (size_t)nTile * 64) * DIMD;

    float chh[2][4][4], ccr[2][4][4];
    mainloop3(chh, ccr, sm0, g_qhi + aB, g_qlo + aB, g_khi + bB, g_klo + bB, tid);

    const float scale = 0.03125f;
    float* S = g_s + (size_t)z * NSEQ * NSEQ;
#pragma unroll
    for (int mt = 0; mt < 2; mt++) {
        const size_t qr = (size_t)mTile * 128 + wR * 32 + mt * 16 + (lane >> 2);
#pragma unroll
        for (int nt = 0; nt < 4; nt++) {
            const int col = nTile * 64 + wC * 32 + nt * 8 + 2 * (lane & 3);
            float v0 = (chh[mt][nt][0] + ccr[mt][nt][0] * LO_INV) * scale;
            float v1 = (chh[mt][nt][1] + ccr[mt][nt][1] * LO_INV) * scale;
            float v2 = (chh[mt][nt][2] + ccr[mt][nt][2] * LO_INV) * scale;
            float v3 = (chh[mt][nt][3] + ccr[mt][nt][3] * LO_INV) * scale;
            *(float2*)&S[qr * NSEQ + col]       = make_float2(v0, v1);
            *(float2*)&S[(qr + 8) * NSEQ + col] = make_float2(v2, v3);
        }
    }
}

// ---------------- conversions ----------------
__global__ void __launch_bounds__(256) conv_x_kernel(const float* __restrict__ f1,
                                                     const float* __restrict__ f2) {
    const float* src = blockIdx.y ? f2 : f1;
    const size_t i4 = (size_t)blockIdx.x * 256 + threadIdx.x;
    float4 v = ((const float4*)src)[i4];
    uint32_t lo0, lo1;
    const uint32_t hi0 = pack_split(v.x, v.y, lo0);
    const uint32_t hi1 = pack_split(v.z, v.w, lo1);
    const size_t off = (size_t)blockIdx.y * NROWS * DIMD;
    ((uint2*)(g_xhi + off))[i4] = make_uint2(hi0, hi1);
    ((uint2*)(g_xlo + off))[i4] = make_uint2(lo0, lo1);
}

__global__ void __launch_bounds__(256) conv_wt_kernel(const float* __restrict__ W) {
    __shared__ float t[32][33];
    const int n0 = blockIdx.x * 32;
    const int k0 = blockIdx.y * 32;
    const int tx = threadIdx.x, ty = threadIdx.y;   // block (32, 8)
#pragma unroll
    for (int r = 0; r < 4; r++)
        t[ty + r * 8][tx] = W[(size_t)(k0 + ty + r * 8) * 3072 + n0 + tx];
    __syncthreads();
#pragma unroll
    for (int r = 0; r < 4; r++) {
        const int n = n0 + ty + r * 8;
        const float x = t[tx][ty + r * 8];
        __half h = __float2half_rn(x);
        __half l = __float2half_rn((x - __half2float(h)) * LO_SCALE);
        g_wthi[(size_t)n * DIMD + k0 + tx] = h;
        g_wtlo[(size_t)n * DIMD + k0 + tx] = l;
    }
}

// ---------------- softmax + top-16 + sparse A@V ----------------
__global__ void __launch_bounds__(256) attn_out_kernel(float* __restrict__ out) {
    const int row = blockIdx.x;
    const int d   = row >> 14;
    const int rem = row & 16383;
    const int b   = rem >> 11;

    const float* s = g_s + (size_t)row * NSEQ;
    const float* V = g_v + ((size_t)(1 - d) * NROWS + (size_t)b * NSEQ) * DIMD;
    float*       o = out + (size_t)d * NOUT + (size_t)rem * DIMD;

    const int tid = threadIdx.x, lane = tid & 31, wid = tid >> 5;

    float l[8];
#pragma unroll
    for (int i = 0; i < 8; i++) l[i] = s[tid + 256 * i];

    __shared__ float sred[8];

    // ---- block max ----
    float m = l[0];
#pragma unroll
    for (int i = 1; i < 8; i++) m = fmaxf(m, l[i]);
#pragma unroll
    for (int off = 16; off; off >>= 1) m = fmaxf(m, __shfl_xor_sync(0xffffffffu, m, off));
    if (!lane) sred[wid] = m;
    __syncthreads();
    m = sred[0];
#pragma unroll
    for (int j = 1; j < 8; j++) m = fmaxf(m, sred[j]);
    __syncthreads();

    // ---- block sum of exp ----
    float se = 0.f;
#pragma unroll
    for (int i = 0; i < 8; i++) se += expf(l[i] - m);
#pragma unroll
    for (int off = 16; off; off >>= 1) se += __shfl_xor_sync(0xffffffffu, se, off);
    if (!lane) sred[wid] = se;
    __syncthreads();
    float denom = sred[0];
#pragma unroll
    for (int j = 1; j < 8; j++) denom += sred[j];
    const float invDen = 1.0f / denom;

    // ---- per-warp top-16 (barrier-free), then single-warp merge ----
    __shared__ float wv[8][16];
    __shared__ int   wi[8][16];
    __shared__ float selv[16];
    __shared__ int   seli[16];
    __shared__ float selw[16];

    float cur[8];
#pragma unroll
    for (int i = 0; i < 8; i++) cur[i] = l[i];

    for (int it = 0; it < 16; ++it) {
        float bv = cur[0];
        int   bi = tid;
#pragma unroll
        for (int i = 1; i < 8; i++) {
            const int idx = tid + 256 * i;
            if (cur[i] > bv || (cur[i] == bv && idx < bi)) { bv = cur[i]; bi = idx; }
        }
#pragma unroll
        for (int off = 16; off; off >>= 1) {
            const float ov = __shfl_xor_sync(0xffffffffu, bv, off);
            const int   oi = __shfl_xor_sync(0xffffffffu, bi, off);
            if (ov > bv || (ov == bv && oi < bi)) { bv = ov; bi = oi; }
        }
        if (!lane) { wv[wid][it] = bv; wi[wid][it] = bi; }
        if ((bi & 255) == tid) cur[bi >> 8] = -FLT_MAX;   // clear winner (owner thread)
    }
    __syncthreads();

    if (wid == 0) {
        // 128 candidates (8 warps x 16); merge top-16
        float cv[4]; int ci[4];
#pragma unroll
        for (int j = 0; j < 4; j++) {
            const int c = lane * 4 + j;
            cv[j] = wv[c >> 4][c & 15];
            ci[j] = wi[c >> 4][c & 15];
        }
        for (int it = 0; it < 16; ++it) {
            float bv = cv[0]; int bi = ci[0];
#pragma unroll
            for (int j = 1; j < 4; j++)
                if (cv[j] > bv || (cv[j] == bv && ci[j] < bi)) { bv = cv[j]; bi = ci[j]; }
#pragma unroll
            for (int off = 16; off; off >>= 1) {
                const float ov = __shfl_xor_sync(0xffffffffu, bv, off);
                const int   oi = __shfl_xor_sync(0xffffffffu, bi, off);
                if (ov > bv || (ov == bv && oi < bi)) { bv = ov; bi = oi; }
            }
            if (!lane) { selv[it] = bv; seli[it] = bi; }
#pragma unroll
            for (int j = 0; j < 4; j++)
                if (ci[j] == bi) cv[j] = -FLT_MAX;
        }
        __syncwarp();
        if (lane < 16) selw[lane] = expf(selv[lane] - m) * invDen;
    }
    __syncthreads();

    // ---- sparse attention-weighted V gather ----
    float4 acc = make_float4(0.f, 0.f, 0.f, 0.f);
#pragma unroll
    for (int j = 0; j < 16; j++) {
        const float  w  = selw[j];
        const float4 vv = *(const float4*)(V + (size_t)seli[j] * DIMD + tid * 4);
        acc.x = fmaf(w, vv.x, acc.x);
        acc.y = fmaf(w, vv.y, acc.y);
        acc.z = fmaf(w, vv.z, acc.z);
        acc.w = fmaf(w, vv.w, acc.w);
    }
    *(float4*)(o + tid * 4) = acc;
}

// ---------------------------------------------------------------------------
extern "C" void kernel_launch(void* const* d_in, const int* in_sizes, int n_in,
                              void* d_out, int out_size) {
    const float* f1 = (const float*)d_in[0];
    const float* f2 = (const float*)d_in[1];
    const float* W  = (const float*)d_in[2];
    float* out = (float*)d_out;

    cudaFuncSetAttribute(gemm_qkv_tc, cudaFuncAttributeMaxDynamicSharedMemorySize, SM_TOTAL);
    cudaFuncSetAttribute(gemm_v_tc, cudaFuncAttributeMaxDynamicSharedMemorySize, SMV_TOTAL);
    cudaFuncSetAttribute(gemm_scores_tc, cudaFuncAttributeMaxDynamicSharedMemorySize, SM_TOTAL);

    conv_x_kernel<<<dim3(16384, 2), 256>>>(f1, f2);
    conv_wt_kernel<<<dim3(96, 32), dim3(32, 8)>>>(W);

    gemm_qkv_tc<<<dim3(32, 128, 2), 256, SM_TOTAL>>>();
    gemm_v_tc<<<dim3(8, 128, 2), 256, SMV_TOTAL>>>();
    gemm_scores_tc<<<dim3(32, 16, 16), 256, SM_TOTAL>>>();

    attn_out_kernel<<<32768, 256>>>(out);
}